// round 6
// baseline (speedup 1.0000x reference)
#include <cuda_runtime.h>
#include <math.h>

#define NB 16
#define NH 16
#define LFR 256
#define L 245760
#define NT 15360          // level-0 tiles of 16 per row
#define TWOPI_F 6.28318530717958647692f
#define RINV ((float)(1.0 / 48000.0))   // fl32(1/48000), eps_R = -2.56e-8

__device__ float g_F[NB * LFR];        // clamped f0
__device__ float g_A[NB * NH * LFR];   // exp(amps)
__device__ float g_E[NB * NH * NT];    // exclusive level-0 tile prefix per row

static __device__ __forceinline__ float fadd(float a, float b) { return __fadd_rn(a, b); }
static __device__ __forceinline__ float fmul(float a, float b) { return __fmul_rn(a, b); }

// reference leaf: fl( fl(f0up * h) * fl(1/48000) )  — reciprocal multiply
static __device__ __forceinline__ float leaf(float f0up, float mh) {
    return __fmul_rn(__fmul_rn(f0up, mh), RINV);
}

// reference-exact interp coords for sample t (mul-then-sub, no fma)
static __device__ __forceinline__ void coords(int t, int& i0, int& i1,
                                              float& w, float& omw) {
    const float C960 = (float)(1.0 / 960.0);
    float a = __fadd_rn((float)t, 0.5f);
    float pos = __fsub_rn(__fmul_rn(a, C960), 0.5f);
    pos = fminf(fmaxf(pos, 0.0f), 255.0f);
    i0 = (int)pos;
    i1 = min(i0 + 1, LFR - 1);
    w = __fsub_rn(pos, (float)i0);
    omw = __fsub_rn(1.0f, w);
}

static __device__ __forceinline__ float f0up_at(const float* __restrict__ sf0, int t) {
    int i0, i1; float w, omw;
    coords(t, i0, i1, w, omw);
    return fadd(fmul(sf0[i0], omw), fmul(sf0[i1], w));
}

// accurate sin, |theta| < 2^18: Cody-Waite 3-term + deg-11 poly
static __device__ __forceinline__ float my_sin(float th) {
    const float I2P = 0.15915494309189533577f;
    const float CA = 6.28125f;
    const float CB = 1.9353071795864769e-3f;
    const float CC = 6.3331253617479151e-11f;
    float k = rintf(__fmul_rn(th, I2P));
    float r = __fmaf_rn(-k, CA, th);
    r = __fmaf_rn(-k, CB, r);
    r = __fmaf_rn(-k, CC, r);
    const float PI_F = 3.14159265358979323846f;
    const float PIH = 1.57079632679489661923f;
    if (r > PIH) r = __fsub_rn(PI_F, r);
    else if (r < -PIH) r = __fsub_rn(-PI_F, r);
    float r2 = __fmul_rn(r, r);
    float p = -2.50521084e-8f;
    p = __fmaf_rn(p, r2, 2.75573192e-6f);
    p = __fmaf_rn(p, r2, -1.98412698e-4f);
    p = __fmaf_rn(p, r2, 8.33333333e-3f);
    p = __fmaf_rn(p, r2, -1.66666667e-1f);
    return __fmaf_rn(__fmul_rn(p, r2), r, r);
}

// ---------------------------------------------------------------------------
__global__ void __launch_bounds__(256) prep_kernel(const float* __restrict__ amps,
                                                   const float* __restrict__ f0) {
    int i = blockIdx.x * 256 + threadIdx.x;
    if (i < NB * LFR) g_F[i] = fmaxf(f0[i], 20.0f);
    if (i < NB * NH * LFR) g_A[i] = expf(amps[i]);
}

// ---------------------------------------------------------------------------
// One block per row (n,h): emulate XLA ReduceWindowRewriter (base 16) over the
// 245760 leaves; emit exclusive level-0 tile prefixes E1.
// levels: 245760 ->(s0) 15360 ->(s1) 960 ->(s2) 60 ->pad64-> 4 -> serial
// ---------------------------------------------------------------------------
__global__ void __launch_bounds__(960) rowscan_kernel() {
    __shared__ float sf0[LFR];
    __shared__ float s1[960];     // level-1 sums (of 16 level-0 tiles)
    __shared__ float in2[960];    // level-2 within-tile prefixes
    __shared__ float s2[60];
    __shared__ float in3[64];
    __shared__ float s3[4];
    __shared__ float r4[4];
    __shared__ float r3[64];
    __shared__ float r2[960];
    int row = blockIdx.x;
    int n = row >> 4;
    float mh = (float)((row & 15) + 1);
    int tid = threadIdx.x;

    if (tid < LFR) sf0[tid] = g_F[n * LFR + tid];
    __syncthreads();

    // thread j (0..959): level-1 tile j = level-0 tiles [16j, 16j+16)
    float pref1[16];
    {
        float acc1 = 0.0f;
#pragma unroll
        for (int ss = 0; ss < 16; ss++) {
            int t0 = (tid * 16 + ss) * 16;
            float a = 0.0f;
#pragma unroll
            for (int s = 0; s < 16; s++)
                a = fadd(a, leaf(f0up_at(sf0, t0 + s), mh));
            acc1 = fadd(acc1, a);
            pref1[ss] = acc1;
        }
        s1[tid] = acc1;
    }
    __syncthreads();

    if (tid < 60) {               // level-2 within-tile prefixes + sums
        float a = 0.0f;
#pragma unroll
        for (int s = 0; s < 16; s++) { a = fadd(a, s1[tid * 16 + s]); in2[tid * 16 + s] = a; }
        s2[tid] = a;
    }
    __syncthreads();
    if (tid < 4) {                // level-3 (60 right-padded to 64)
        float a = 0.0f;
#pragma unroll
        for (int s = 0; s < 16; s++) {
            int i = tid * 16 + s;
            float v = (i < 60) ? s2[i] : 0.0f;
            a = fadd(a, v);
            in3[i] = a;
        }
        s3[tid] = a;
    }
    __syncthreads();
    if (tid == 0) {               // level-4 base case: serial fold
        float a = 0.0f;
#pragma unroll
        for (int p = 0; p < 4; p++) { a = fadd(a, s3[p]); r4[p] = a; }
    }
    __syncthreads();
    if (tid < 64)
        r3[tid] = (tid < 16) ? in3[tid] : fadd(in3[tid], r4[(tid >> 4) - 1]);
    __syncthreads();
    r2[tid] = (tid < 16) ? in2[tid] : fadd(in2[tid], r3[(tid >> 4) - 1]);
    __syncthreads();

    float E2 = (tid == 0) ? 0.0f : r2[tid - 1];
    float* Erow = g_E + row * NT;
    if (tid == 0) Erow[0] = 0.0f;
#pragma unroll
    for (int ss = 0; ss < 16; ss++) {
        int q = tid * 16 + ss;
        float r1 = fadd(pref1[ss], E2);
        if (q + 1 < NT) Erow[q + 1] = r1;
    }
}

// ---------------------------------------------------------------------------
// Oscillator: thread per (n, level-0 tile). Serial within-tile prefix per h,
// dt = fl(inner + E1), theta = fl(2pi*dt), serial h-sum, *1/16.
// ---------------------------------------------------------------------------
__global__ void __launch_bounds__(256) osc_kernel(float* __restrict__ out) {
    __shared__ float sA[NH * LFR];
    __shared__ float sf0[LFR];
    int n = blockIdx.y;
    int tid = threadIdx.x;
    for (int i = tid; i < NH * LFR; i += 256) sA[i] = g_A[n * NH * LFR + i];
    if (tid < LFR) sf0[tid] = g_F[n * LFR + tid];
    __syncthreads();

    int q = blockIdx.x * 256 + tid;
    float run[NH], Ev[NH];
#pragma unroll
    for (int h = 0; h < NH; h++) {
        run[h] = 0.0f;
        Ev[h] = g_E[((n << 4) + h) * NT + q];
    }
    int t0 = q * 16;
#pragma unroll
    for (int s = 0; s < 16; s++) {
        int t = t0 + s;
        int i0, i1; float w, omw;
        coords(t, i0, i1, w, omw);
        float f0up = fadd(fmul(sf0[i0], omw), fmul(sf0[i1], w));
        float wave = 0.0f;
#pragma unroll
        for (int h = 0; h < NH; h++) {
            float lv = leaf(f0up, (float)(h + 1));
            run[h] = fadd(run[h], lv);
            float dt = fadd(run[h], Ev[h]);
            float theta = __fmul_rn(TWOPI_F, dt);
            float sv = my_sin(theta);
            float amp = fadd(fmul(sA[h * LFR + i0], omw), fmul(sA[h * LFR + i1], w));
            wave = fadd(wave, fmul(sv, amp));
        }
        out[n * L + t] = __fmul_rn(wave, 0.0625f);
    }
}

// ---------------------------------------------------------------------------
extern "C" void kernel_launch(void* const* d_in, const int* in_sizes, int n_in,
                              void* d_out, int out_size) {
    const float* amps = (const float*)d_in[0];
    const float* f0 = (const float*)d_in[1];
    if (n_in >= 2 && in_sizes[0] == NB * LFR && in_sizes[1] == NB * NH * LFR) {
        const float* tmp = amps; amps = f0; f0 = tmp;
    }
    float* out = (float*)d_out;

    prep_kernel<<<(NB * NH * LFR + 255) / 256, 256>>>(amps, f0);
    rowscan_kernel<<<NB * NH, 960>>>();
    osc_kernel<<<dim3(NT / 256, NB), 256>>>(out);
}